// round 11
// baseline (speedup 1.0000x reference)
#include <cuda_runtime.h>
#include <cuda_bf16.h>
#include <cstdint>

typedef __nv_bfloat16 bf;
#define SEQ  512
#define NTHR 256
#define STG  24576
#define SMTOT (4*STG + 1280 + 8192)
#define SW(o) ((o) ^ (((o) >> 3) & 0x70))

__device__ __align__(1024) bf g_xh[128][65536];
__device__ __align__(1024) bf g_xl[128][65536];
__device__ __align__(1024) bf g_w0h[2048][1152];
__device__ __align__(1024) bf g_w0l[2048][1152];
__device__ __align__(1024) bf g_w1h[2048][2048];
__device__ __align__(1024) bf g_w1l[2048][2048];
__device__ __align__(1024) bf g_hh[2][2][128][1024];  // [layer][ping][row][unit]
__device__ __align__(1024) bf g_hl[2][2][128][1024];
__device__ float    g_biasP[2][2048];
__device__ unsigned g_flags[128 * 32];

__device__ __forceinline__ uint32_t s2u(const void* p) {
    uint32_t a;
    asm("{ .reg .u64 t; cvta.to.shared.u64 t, %1; cvt.u32.u64 %0, t; }" : "=r"(a) : "l"(p));
    return a;
}
__device__ __forceinline__ void cp16(uint32_t dst, const void* src) {
    asm volatile("cp.async.cg.shared.global [%0], [%1], 16;" :: "r"(dst), "l"(src));
}
__device__ __forceinline__ void cpc() { asm volatile("cp.async.commit_group;"); }
__device__ __forceinline__ void cpw_n(int n) {
    if (n <= 0)      asm volatile("cp.async.wait_group 0;");
    else if (n == 1) asm volatile("cp.async.wait_group 1;");
    else             asm volatile("cp.async.wait_group 2;");
}
__device__ __forceinline__ void ldmx4(unsigned* r, uint32_t a) {
    asm volatile("ldmatrix.sync.aligned.m8n8.x4.shared.b16 {%0,%1,%2,%3}, [%4];"
        : "=r"(r[0]), "=r"(r[1]), "=r"(r[2]), "=r"(r[3]) : "r"(a));
}
__device__ __forceinline__ void mma(float* c, const unsigned* a, const unsigned* b) {
    asm volatile("mma.sync.aligned.m16n8k16.row.col.f32.bf16.bf16.f32 "
        "{%0,%1,%2,%3}, {%4,%5,%6,%7}, {%8,%9}, {%0,%1,%2,%3};"
        : "+f"(c[0]), "+f"(c[1]), "+f"(c[2]), "+f"(c[3])
        : "r"(a[0]), "r"(a[1]), "r"(a[2]), "r"(a[3]), "r"(b[0]), "r"(b[1]));
}
__device__ __forceinline__ void gbar(unsigned& gen) {
    gen++;
    __syncthreads();
    if (threadIdx.x == 0)
        asm volatile("st.release.gpu.global.u32 [%0], %1;"
                     :: "l"(&g_flags[blockIdx.x * 32]), "r"(gen) : "memory");
    if (threadIdx.x < 128) {
        const unsigned* f = &g_flags[threadIdx.x * 32];
        unsigned v;
        do {
            asm volatile("ld.acquire.gpu.global.u32 %0, [%1];" : "=r"(v) : "l"(f) : "memory");
            if (v < gen) __nanosleep(32);
        } while (v < gen);
    }
    __syncthreads();
}

__global__ void __launch_bounds__(NTHR, 1) gru_mma(
    const float* __restrict__ Wfc, const float* __restrict__ bfc,
    float* __restrict__ out) {
    extern __shared__ __align__(1024) char sm[];
    const uint32_t sb = s2u(sm);
    const int tid = threadIdx.x, warp = tid >> 5, lane = tid & 31;
    const int ctan = blockIdx.x & 63, ctam = blockIdx.x >> 6;
    float* sbias = (float*)(sm + 4 * STG);
    float* sred  = sbias + 64;
    float* redK  = (float*)(sm + 4 * STG + 1280);   // 4 warps x 32 lanes x 16 f
    if (tid < 64) sbias[tid] = g_biasP[tid >> 5][ctan * 32 + (tid & 31)];
    __syncthreads();

    const int wm = warp & 3;            // m-quarter (m16)
    const int kh = warp >> 2;           // k-half (k32)
    const uint32_t aoffA = (wm * 16 + (lane & 15)) * 128 + (lane >> 4) * 16;
    const uint32_t boff0 = (((lane >> 4) & 1) * 8 + (lane & 7)) * 128 + ((lane >> 3) & 1) * 16;
    const uint32_t boff1 = boff0 + 16 * 128;
    unsigned gen = 0; int p = 0;
    int pcnt = 0, ccnt = 0;
    float acc[4][4];

    auto stageF = [&](int lay, int tt, int pp, int c) {
        const bf *ah, *al; long rstr; int ko;
        if (!lay) {
            if (c < 2) { ah = &g_xh[0][0]; al = &g_xl[0][0]; rstr = 65536; ko = tt * 128 + c * 64; }
            else { ah = &g_hh[0][pp][0][0]; al = &g_hl[0][pp][0][0]; rstr = 1024; ko = (c - 2) * 64; }
        } else {
            if (c < 16) { ah = &g_hh[0][pp ^ 1][0][0]; al = &g_hl[0][pp ^ 1][0][0]; rstr = 1024; ko = c * 64; }
            else { ah = &g_hh[1][pp][0][0]; al = &g_hl[1][pp][0][0]; rstr = 1024; ko = (c - 16) * 64; }
        }
        const bf* wh = lay ? &g_w1h[0][0] : &g_w0h[0][0];
        const bf* wl = lay ? &g_w1l[0][0] : &g_w0l[0][0];
        const long Kst = lay ? 2048 : 1152;
        uint32_t db = sb + (pcnt & 3) * STG;
        #pragma unroll
        for (int it = 0; it < 4; it++) {
            int idx = it * NTHR + tid, d = idx >> 9, r = (idx >> 3) & 63, u = idx & 7;
            cp16(db + d * 8192 + SW(r * 128 + u * 16),
                 (d ? al : ah) + (long)(ctam * 64 + r) * rstr + ko + u * 8);
        }
        #pragma unroll
        for (int it = 0; it < 2; it++) {
            int idx = it * NTHR + tid, d = idx >> 8, r = (idx >> 3) & 31, u = idx & 7;
            cp16(db + 16384 + d * 4096 + SW(r * 128 + u * 16),
                 (d ? wl : wh) + (long)(ctan * 32 + r) * Kst + c * 64 + u * 8);
        }
        cpc(); pcnt++;
    };

    auto computeC = [&]() {
        uint32_t tb = sb + (ccnt & 3) * STG;
        #pragma unroll
        for (int kk = 0; kk < 2; kk++) {
            const uint32_t ko = kh * 64 + kk * 32;
            unsigned ah[4], al[4], bh[8], bl[8];
            ldmx4(ah, tb + SW(aoffA + ko));
            ldmx4(al, tb + 8192 + SW(aoffA + ko));
            ldmx4(bh,     tb + 16384 + SW(boff0 + ko));
            ldmx4(bh + 4, tb + 16384 + SW(boff1 + ko));
            ldmx4(bl,     tb + 20480 + SW(boff0 + ko));
            ldmx4(bl + 4, tb + 20480 + SW(boff1 + ko));
            #pragma unroll
            for (int j = 0; j < 4; j++) mma(acc[j], ah, bh + 2 * j);
            #pragma unroll
            for (int j = 0; j < 4; j++) mma(acc[j], ah, bl + 2 * j);
            #pragma unroll
            for (int j = 0; j < 4; j++) mma(acc[j], al, bh + 2 * j);
        }
        ccnt++;
    };

    auto epi = [&](int lay) {
        __syncthreads();
        if (kh == 1) {
            float4* rb = (float4*)redK + (wm * 32 + lane) * 4;
            #pragma unroll
            for (int j = 0; j < 4; j++)
                rb[j] = make_float4(acc[j][0], acc[j][1], acc[j][2], acc[j][3]);
        }
        __syncthreads();
        if (kh == 0) {
            const float4* rb = (const float4*)redK + (wm * 32 + lane) * 4;
            #pragma unroll
            for (int j = 0; j < 4; j++) {
                float4 v = rb[j];
                acc[j][0] += v.x; acc[j][1] += v.y; acc[j][2] += v.z; acc[j][3] += v.w;
            }
            bf* hh = &g_hh[lay][p ^ 1][0][0];  bf* hl = &g_hl[lay][p ^ 1][0][0];
            const bf* qh = &g_hh[lay][p][0][0]; const bf* ql = &g_hl[lay][p][0][0];
            const int r0 = ctam * 64 + wm * 16 + (lane >> 2);
            #pragma unroll
            for (int j = 0; j < 4; j++) {
                int ul = j * 4 + (lane & 3);
                int ug = ctan * 16 + ul;
                float bz = sbias[lay * 32 + 2 * ul], bn = sbias[lay * 32 + 2 * ul + 1];
                #pragma unroll
                for (int rr = 0; rr < 2; rr++) {
                    int r = r0 + rr * 8;
                    float z = 1.f / (1.f + __expf(-(acc[j][rr * 2] + bz)));
                    float e = __expf(2.f * (acc[j][rr * 2 + 1] + bn));
                    float nn = __fdividef(e - 1.f, e + 1.f);
                    float hp = __bfloat162float(qh[r * 1024 + ug]) + __bfloat162float(ql[r * 1024 + ug]);
                    float hv = (1.f - z) * nn + z * hp;
                    bf hi = __float2bfloat16(hv);
                    hh[r * 1024 + ug] = hi;
                    hl[r * 1024 + ug] = __float2bfloat16(hv - __bfloat162float(hi));
                }
            }
        }
        __syncthreads();
    };

    stageF(0, 0, 0, 0); stageF(0, 0, 0, 1); stageF(0, 0, 0, 2);

    for (int t = 0; t < SEQ; t++) {
        #pragma unroll
        for (int j = 0; j < 4; j++) acc[j][0]=acc[j][1]=acc[j][2]=acc[j][3]=0.f;
        for (int c = 0; c < 18; c++) {
            cpw_n(pcnt - ccnt - 1);
            __syncthreads();
            if (c + 3 < 18) stageF(0, t, p, c + 3);
            computeC();
        }
        epi(0);
        gbar(gen);
        stageF(1, t, p, 0); stageF(1, t, p, 1); stageF(1, t, p, 2);
        #pragma unroll
        for (int j = 0; j < 4; j++) acc[j][0]=acc[j][1]=acc[j][2]=acc[j][3]=0.f;
        for (int c = 0; c < 32; c++) {
            cpw_n(pcnt - ccnt - 1);
            __syncthreads();
            if (c + 3 < 32) stageF(1, t, p, c + 3);
            else if (t + 1 < SEQ) stageF(0, t + 1, p ^ 1, c + 3 - 32);
            computeC();
        }
        epi(1);
        p ^= 1;
    }
    gbar(gen);

    const bf* fh = &g_hh[1][p][0][0];
    const bf* fl = &g_hl[1][p][0][0];
    const int row = blockIdx.x;
    float part = 0.f;
    for (int j = tid; j < 1024; j += NTHR)
        part += (__bfloat162float(fh[row * 1024 + j]) + __bfloat162float(fl[row * 1024 + j])) * Wfc[j];
    sred[tid] = part;
    __syncthreads();
    if (tid == 0) {
        float s = 0.f;
        #pragma unroll 8
        for (int i = 0; i < NTHR; i++) s += sred[i];
        out[row] = s + bfc[0];
    }
}

__global__ void ginit(const float* __restrict__ x,
                      const float* __restrict__ b0, const float* __restrict__ b1) {
    long i = (long)blockIdx.x * blockDim.x + threadIdx.x;
    long st = (long)gridDim.x * blockDim.x;
    for (long idx = i; idx < 128L * 65536; idx += st) {
        float v = x[idx];
        bf h = __float2bfloat16(v);
        ((bf*)g_xh)[idx] = h;
        ((bf*)g_xl)[idx] = __float2bfloat16(v - __bfloat162float(h));
    }
    bf z = __float2bfloat16(0.f);
    for (long idx = i; idx < 2L * 2 * 128 * 1024; idx += st) {
        ((bf*)g_hh)[idx] = z; ((bf*)g_hl)[idx] = z;
    }
    if (i < 128 * 32) g_flags[i] = 0u;
    if (i < 4096) {
        int l = (int)(i >> 11), g = (int)(i & 2047);
        int u = g >> 1, col = (g & 1) ? 2048 + u : u;
        g_biasP[l][g] = l ? b1[col] : b0[col];
    }
}

__global__ void prepw(const float* __restrict__ W0, const float* __restrict__ W1) {
    const int l = blockIdx.z;
    const float* W = l ? W1 : W0;
    bf* Dh = l ? &g_w1h[0][0] : &g_w0h[0][0];
    bf* Dl = l ? &g_w1l[0][0] : &g_w0l[0][0];
    const int K = l ? 2048 : 1152;
    const int k0 = blockIdx.x * 32; if (k0 >= K) return;
    const int g0 = blockIdx.y * 32;
    __shared__ float tile[32][33];
    const int tx = threadIdx.x, ty = threadIdx.y;
    {
        int g = g0 + tx, u = g >> 1, col = (g & 1) ? 2048 + u : u;
        #pragma unroll
        for (int r = 0; r < 32; r += 8)
            tile[ty + r][tx] = W[(size_t)(k0 + ty + r) * 3072 + col];
    }
    __syncthreads();
    #pragma unroll
    for (int r = 0; r < 32; r += 8) {
        float v = tile[tx][ty + r];
        bf h = __float2bfloat16(v);
        size_t o = (size_t)(g0 + ty + r) * K + k0 + tx;
        Dh[o] = h;
        Dl[o] = __float2bfloat16(v - __bfloat162float(h));
    }
}

extern "C" void kernel_launch(void* const* d_in, const int* in_sizes, int n_in,
                              void* d_out, int out_size) {
    const float* x   = (const float*)d_in[0];
    const float* W0  = (const float*)d_in[1];
    const float* b0  = (const float*)d_in[2];
    const float* W1  = (const float*)d_in[3];
    const float* b1  = (const float*)d_in[4];
    const float* Wfc = (const float*)d_in[5];
    const float* bfc = (const float*)d_in[6];
    float* out = (float*)d_out;

    cudaFuncSetAttribute(gru_mma, cudaFuncAttributeMaxDynamicSharedMemorySize, SMTOT);
    ginit<<<2048, 256>>>(x, b0, b1);
    prepw<<<dim3(64, 64, 2), dim3(32, 8)>>>(W0, W1);
    gru_mma<<<128, NTHR, SMTOT>>>(Wfc, bfc, out);
}